// round 17
// baseline (speedup 1.0000x reference)
#include <cuda_runtime.h>

// NashCascadeNetwork: 8 layers x 524288 buckets, 8 spigots/bucket.
// Inputs (metadata order): H[NB] f32, S[NB,8,2] f32, theta[NB*8] f32, precip[1] f32
// Output (f32): [ H_new(NB) | s_q(NB*8) | network_outflow(1) ]
//
// v8 256-bit memory ops + 4 buckets per thread, 256-thread blocks (1024
// buckets/block, grid 4096): minimal block-count amortization of the
// boundary recompute + prologue, __ldcs on every bulk stream.

#define NB          4194304
#define NS          8
#define BPL         524288                   // buckets in last layer
#define NTHREADS    256
#define NSETS       4
#define BPB         1024                     // buckets per block (4 per thread)
#define NWARPS      (NTHREADS / 32)          // 8
#define NGRID       (NB / BPB)               // 4096
#define FIRST_LAST  ((NB - BPL) / BPB)       // 3584
#define NLASTBLK    (BPL / BPB)              // 512
#define OUT_SQ_OFF  NB
#define OUT_SCALAR  (NB * (NS + 1))          // 37748736

__device__ double   g_partials[NLASTBLK];
__device__ unsigned g_count = 0;

struct v8 { float x0,x1,x2,x3,x4,x5,x6,x7; };

__device__ __forceinline__ v8 ldcs_v8(const float* p) {
    v8 r;
    asm volatile("ld.global.cs.v8.b32 {%0,%1,%2,%3,%4,%5,%6,%7}, [%8];"
        : "=f"(r.x0), "=f"(r.x1), "=f"(r.x2), "=f"(r.x3),
          "=f"(r.x4), "=f"(r.x5), "=f"(r.x6), "=f"(r.x7)
        : "l"(p));
    return r;
}

__device__ __forceinline__ void stcs_v8(float* p, float a0, float a1, float a2, float a3,
                                                  float a4, float a5, float a6, float a7) {
    asm volatile("st.global.cs.v8.b32 [%0], {%1,%2,%3,%4,%5,%6,%7,%8};"
        :: "l"(p),
           "f"(a0), "f"(a1), "f"(a2), "f"(a3),
           "f"(a4), "f"(a5), "f"(a6), "f"(a7)
        : "memory");
}

// q = theta * sqrt(2*9.8*h) * 0.5*(tanh(h)+1) * area,  h = max(0, H - height)
// 0.5*(tanh(h)+1) == sigmoid(2h) == 1/(1+exp(-2h))  -> EX2 + RCP (err ~1e-7)
__device__ __forceinline__ float spigot_q(float Hb, float sh, float sa, float th) {
    float h = fmaxf(0.0f, Hb - sh);
    float e = __expf(-2.0f * h);
    float mod;
    asm("rcp.approx.f32 %0, %1;" : "=f"(mod) : "f"(1.0f + e));
    float s;
    asm("sqrt.approx.f32 %0, %1;" : "=f"(s) : "f"(19.6f * h));
    return th * s * mod * sa;
}

__global__ __launch_bounds__(NTHREADS)
void nash_main(const float* __restrict__ H,
               const float* __restrict__ S,      // [NB*16]
               const float* __restrict__ T,      // [NB*8]
               const float* __restrict__ precip,
               float* __restrict__ out)
{
    float* Hn = out;
    float* SQ = out + OUT_SQ_OFF;

    const int tid  = threadIdx.x;
    const int lane = tid & 31;
    const int warp = tid >> 5;
    const int base = blockIdx.x * BPB + tid;

    // ---- front-batched streaming loads: 4 buckets = 12x256b + 4x32b ----
    float Hv[NSETS];
    v8 sa[NSETS], sb[NSETS], tv[NSETS];
    #pragma unroll
    for (int k = 0; k < NSETS; k++) {
        const int b = base + k * NTHREADS;
        Hv[k] = __ldcs(&H[b]);
        sa[k] = ldcs_v8(S + (size_t)b * 16);
        sb[k] = ldcs_v8(S + (size_t)b * 16 + 8);
        tv[k] = ldcs_v8(T + (size_t)b * 8);
    }

    // ---- block-boundary bucket (b0-1): warp 0, lanes 0-7, one spigot each ----
    float pe = 0.0f;
    if (warp == 0) {
        if (blockIdx.x != 0 && lane < 8) {
            const int    bp = blockIdx.x * BPB - 1;
            const float  Hp = H[bp];
            const float2 sp = ((const float2*)S)[(size_t)bp * 8 + lane];
            const float  tp = T[(size_t)bp * 8 + lane];
            pe = spigot_q(Hp, sp.x, sp.y, tp);
        }
        pe += __shfl_xor_sync(0xffffffffu, pe, 1);
        pe += __shfl_xor_sync(0xffffffffu, pe, 2);
        pe += __shfl_xor_sync(0xffffffffu, pe, 4);   // lane 0 = full sum
    }

    // ---- 8 spigots per bucket, all in-register ----
    float ob[NSETS];
    #pragma unroll
    for (int k = 0; k < NSETS; k++) {
        const int b = base + k * NTHREADS;
        const float q0 = spigot_q(Hv[k], sa[k].x0, sa[k].x1, tv[k].x0);
        const float q1 = spigot_q(Hv[k], sa[k].x2, sa[k].x3, tv[k].x1);
        const float q2 = spigot_q(Hv[k], sa[k].x4, sa[k].x5, tv[k].x2);
        const float q3 = spigot_q(Hv[k], sa[k].x6, sa[k].x7, tv[k].x3);
        const float q4 = spigot_q(Hv[k], sb[k].x0, sb[k].x1, tv[k].x4);
        const float q5 = spigot_q(Hv[k], sb[k].x2, sb[k].x3, tv[k].x5);
        const float q6 = spigot_q(Hv[k], sb[k].x4, sb[k].x5, tv[k].x6);
        const float q7 = spigot_q(Hv[k], sb[k].x6, sb[k].x7, tv[k].x7);
        stcs_v8(SQ + (size_t)b * 8, q0, q1, q2, q3, q4, q5, q6, q7);
        ob[k] = ((q0 + q1) + (q2 + q3)) + ((q4 + q5) + (q6 + q7));
    }

    // ---- inflow[b] = outflow[b-1]: shfl_up per set + smem warp carries ----
    __shared__ float c[NSETS][NWARPS];
    float in[NSETS];
    #pragma unroll
    for (int k = 0; k < NSETS; k++) {
        in[k] = __shfl_up_sync(0xffffffffu, ob[k], 1);
        if (lane == 31) c[k][warp] = ob[k];
    }
    __syncthreads();
    if (lane == 0) {
        #pragma unroll
        for (int k = 0; k < NSETS; k++) {
            if (warp == 0)
                in[k] = (k == 0)
                      ? ((blockIdx.x == 0) ? __ldg(precip) : pe)
                      : c[k - 1][NWARPS - 1];   // local bucket k*256-1
            else
                in[k] = c[k][warp - 1];
        }
    }
    #pragma unroll
    for (int k = 0; k < NSETS; k++)
        __stcs(&Hn[base + k * NTHREADS], Hv[k] + in[k] - ob[k]);

    // ---- last-layer network-outflow reduction (last 12.5% of blocks) ----
    if (blockIdx.x >= FIRST_LAST) {
        double a = ((double)ob[0] + (double)ob[1])
                 + ((double)ob[2] + (double)ob[3]);
        a += __shfl_xor_sync(0xffffffffu, a, 16);
        a += __shfl_xor_sync(0xffffffffu, a, 8);
        a += __shfl_xor_sync(0xffffffffu, a, 4);
        a += __shfl_xor_sync(0xffffffffu, a, 2);
        a += __shfl_xor_sync(0xffffffffu, a, 1);

        __shared__ double sd[NWARPS];
        __shared__ bool   s_last;
        if (tid == 0) s_last = false;
        if (lane == 0) sd[warp] = a;
        __syncthreads();
        if (tid == 0) {
            double bs = ((sd[0] + sd[1]) + (sd[2] + sd[3]))
                      + ((sd[4] + sd[5]) + (sd[6] + sd[7]));
            g_partials[blockIdx.x - FIRST_LAST] = bs;
            __threadfence();
            unsigned t = atomicAdd(&g_count, 1u);
            if (t == NLASTBLK - 1) s_last = true;
        }
        __syncthreads();

        if (s_last) {
            // Last block alive: fixed-order reduction (bit-deterministic).
            __threadfence();
            double acc = 0.0;
            #pragma unroll 2
            for (int i = tid; i < NLASTBLK; i += NTHREADS)
                acc += g_partials[i];
            __shared__ double sm[NTHREADS];
            sm[tid] = acc;
            __syncthreads();
            #pragma unroll
            for (int s = NTHREADS / 2; s > 0; s >>= 1) {
                if (tid < s) sm[tid] += sm[tid + s];
                __syncthreads();
            }
            if (tid == 0) {
                out[OUT_SCALAR] = (float)sm[0];
                g_count = 0;                     // reset for graph replay
            }
        }
    }
}

extern "C" void kernel_launch(void* const* d_in, const int* in_sizes, int n_in,
                              void* d_out, int out_size) {
    const float* H      = (const float*)d_in[0];
    const float* S      = (const float*)d_in[1];
    const float* T      = (const float*)d_in[2];
    const float* precip = (const float*)d_in[3];

    nash_main<<<NGRID, NTHREADS>>>(H, S, T, precip, (float*)d_out);
}